// round 5
// baseline (speedup 1.0000x reference)
#include <cuda_runtime.h>
#include <cuda_bf16.h>
#include <cstdint>
#include <cstddef>

// Problem constants
#define BB 4
#define SS 4096
#define HH 768
#define RR 242
#define HK 256
#define CP 256
#define RWIN 16
#define NFREQ 384

// ---------------- device scratch ---------------------------------------------------------
__device__ float g_z [(size_t)BB * SS * CP];
__device__ float g_z2[(size_t)BB * SS * CP];
__device__ float g_T1t[RR * RR];
__device__ float g_WcT[HH * CP];
__device__ float g_e[RWIN + 1];
__device__ __nv_bfloat16 g_vlh[CP * HH];   // v_low hi (rows 242..255 zero)
__device__ __nv_bfloat16 g_vll[CP * HH];   // v_low lo
__device__ __nv_bfloat16 g_wch[HH * CP];   // WcT hi
__device__ __nv_bfloat16 g_wcl[HH * CP];   // WcT lo

// ---------------- band weight precompute -------------------------------------------------
__global__ void prep_kernel() {
    int w    = threadIdx.x >> 5;
    int lane = threadIdx.x & 31;
    if (w > RWIN) return;
    float d = (float)w;
    float s = 0.f;
    for (int j = lane; j < NFREQ; j += 32) {
        float f = expf(-(float)j * (9.210340371976184f / (float)NFREQ));
        s += cosf(d * f);
    }
    #pragma unroll
    for (int o = 16; o > 0; o >>= 1) s += __shfl_down_sync(0xffffffffu, s, o);
    if (lane == 0) g_e[w] = expf(s - (float)NFREQ);
}

// ---------------- small NN gemm ----------------------------------------------------------
__global__ void gemm_nn_small(const float* __restrict__ A, int lda,
                              const float* __restrict__ B, int ldb,
                              float* __restrict__ C, int ldc,
                              int M, int N, int K) {
    __shared__ float As[16][17];
    __shared__ float Bs[16][17];
    int tx = threadIdx.x, ty = threadIdx.y;
    int m = blockIdx.y * 16 + ty;
    int n = blockIdx.x * 16 + tx;
    float acc = 0.f;
    for (int k0 = 0; k0 < K; k0 += 16) {
        As[ty][tx] = (m < M && (k0 + tx) < K) ? A[(size_t)m * lda + k0 + tx] : 0.f;
        Bs[ty][tx] = ((k0 + ty) < K && n < N) ? B[(size_t)(k0 + ty) * ldb + n] : 0.f;
        __syncthreads();
        #pragma unroll
        for (int k = 0; k < 16; k++) acc += As[ty][k] * Bs[k][tx];
        __syncthreads();
    }
    if (m < M && n < N) C[(size_t)m * ldc + n] = acc;
}

// ---------------- weight pre-conversion: fp32 -> bf16 hi/lo, with row zero-pad -----------
__global__ void conv_hilo(const float* __restrict__ src, int rows_src, int cols,
                          __nv_bfloat16* __restrict__ hi, __nv_bfloat16* __restrict__ lo,
                          int rows_dst) {
    int idx = blockIdx.x * 256 + threadIdx.x;
    if (idx >= rows_dst * cols) return;
    int r = idx / cols;
    float v = (r < rows_src) ? src[idx] : 0.f;
    __nv_bfloat16 h = __float2bfloat16_rn(v);
    hi[idx] = h;
    lo[idx] = __float2bfloat16_rn(v - __bfloat162float(h));
}

// ---------------- bf16 / mma helpers -----------------------------------------------------
__device__ __forceinline__ uint32_t pack_bf16x2(float lo_elem, float hi_elem) {
    uint32_t r;
    asm("cvt.rn.bf16x2.f32 %0, %1, %2;" : "=r"(r) : "f"(hi_elem), "f"(lo_elem));
    return r;
}
__device__ __forceinline__ void cvt_pair(float e0, float e1, uint32_t& hi, uint32_t& lo) {
    hi = pack_bf16x2(e0, e1);
    float h0 = __uint_as_float(hi << 16);
    float h1 = __uint_as_float(hi & 0xffff0000u);
    lo = pack_bf16x2(e0 - h0, e1 - h1);
}
__device__ __forceinline__ void mma_bf16(float* d, const uint32_t* a, uint32_t b0, uint32_t b1) {
    asm volatile(
        "mma.sync.aligned.m16n8k16.row.col.f32.bf16.bf16.f32 "
        "{%0,%1,%2,%3}, {%4,%5,%6,%7}, {%8,%9}, {%0,%1,%2,%3};"
        : "+f"(d[0]), "+f"(d[1]), "+f"(d[2]), "+f"(d[3])
        : "r"(a[0]), "r"(a[1]), "r"(a[2]), "r"(a[3]), "r"(b0), "r"(b1));
}
__device__ __forceinline__ uint32_t smem_u32(const void* p) {
    uint32_t a;
    asm("{ .reg .u64 t; cvta.to.shared.u64 t, %1; cvt.u32.u64 %0, t; }" : "=r"(a) : "l"(p));
    return a;
}
__device__ __forceinline__ void cp16(uint32_t dst, const void* src) {
    asm volatile("cp.async.cg.shared.global [%0], [%1], 16;" :: "r"(dst), "l"(src));
}
__device__ __forceinline__ void cp_commit() {
    asm volatile("cp.async.commit_group;" ::: "memory");
}
template<int N> __device__ __forceinline__ void cp_wait() {
    asm volatile("cp.async.wait_group %0;" :: "n"(N) : "memory");
}

// ---------------- pipelined tensor-core GEMM: C[M,N] = A_f32[M,K] @ B_bf16[N,K]^T --------
// 3-term split: A converted hi/lo in registers; B pre-split (Bh, Bl) in gmem.
// BM=BN=128, BK=32; 256 threads = 8 warps (4M x 2N), warp tile 32x64.
// M%128==0, N = grid.x*128, K%32==0, K>=64.
#define A_PITCH 40                     // floats per A smem row
#define B_PITCH 20                     // u32 per B smem row
#define A_U32 (128 * A_PITCH)          // 5120 u32 = 20480 B
#define B_U32 (128 * B_PITCH)          // 2560 u32 = 10240 B
#define STAGE_U32 (A_U32 + 2 * B_U32)  // 10240 u32 = 40960 B
#define SM_BYTES (2 * STAGE_U32 * 4)   // 81920 B

__global__ void __launch_bounds__(256, 2)
mma_gemm_abt(const float* __restrict__ A, int lda,
             const __nv_bfloat16* __restrict__ Bh,
             const __nv_bfloat16* __restrict__ Bl, int ldb,
             float* __restrict__ C, int ldc, int K) {
    extern __shared__ uint32_t sm4[];
    const uint32_t sb = smem_u32(sm4);
    const int tid  = threadIdx.x;
    const int wid  = tid >> 5;
    const int lane = tid & 31;
    const int m0 = blockIdx.y * 128;
    const int n0 = blockIdx.x * 128;
    const int mbw = (wid & 3) * 32;
    const int nbw = (wid >> 2) * 64;
    const int lr = lane >> 2;
    const int lc = lane & 3;

    // fill indices
    const int ar = tid >> 3, ac = tid & 7;   // A: rows ar+32i, 16B chunk ac
    const int br = tid >> 2, bc = tid & 3;   // B: rows br+64i, 16B chunk bc

    const float* aSrc = A + (size_t)(m0 + ar) * lda + ac * 4;
    const __nv_bfloat16* bhSrc = Bh + (size_t)(n0 + br) * ldb + bc * 8;
    const __nv_bfloat16* blSrc = Bl + (size_t)(n0 + br) * ldb + bc * 8;
    const uint32_t aDst  = sb + (ar * A_PITCH + ac * 4) * 4;
    const uint32_t bhDst = sb + (A_U32 + br * B_PITCH + bc * 4) * 4;
    const uint32_t blDst = sb + (A_U32 + B_U32 + br * B_PITCH + bc * 4) * 4;

    float acc[2][8][4] = {};
    const int nchunks = K >> 5;

    #define ISSUE(ch) do {                                                          \
        const uint32_t so_ = ((ch) & 1) * (STAGE_U32 * 4);                          \
        const int k0_ = (ch) << 5;                                                  \
        _Pragma("unroll")                                                           \
        for (int i_ = 0; i_ < 4; i_++)                                              \
            cp16(aDst + so_ + i_ * 32 * A_PITCH * 4,                                \
                 aSrc + k0_ + (size_t)i_ * 32 * lda);                               \
        _Pragma("unroll")                                                           \
        for (int i_ = 0; i_ < 2; i_++) {                                            \
            cp16(bhDst + so_ + i_ * 64 * B_PITCH * 4,                               \
                 bhSrc + k0_ + (size_t)i_ * 64 * ldb);                              \
            cp16(blDst + so_ + i_ * 64 * B_PITCH * 4,                               \
                 blSrc + k0_ + (size_t)i_ * 64 * ldb);                              \
        }                                                                           \
        cp_commit();                                                                \
    } while (0)

    ISSUE(0);
    for (int ch = 0; ch < nchunks; ch++) {
        if (ch + 1 < nchunks) { ISSUE(ch + 1); cp_wait<1>(); }
        else                  { cp_wait<0>(); }
        __syncthreads();

        const uint32_t stg = (ch & 1) * STAGE_U32;
        const float* As = (const float*)(sm4 + stg);
        const uint32_t* BHs = sm4 + stg + A_U32;
        const uint32_t* BLs = sm4 + stg + A_U32 + B_U32;

        #pragma unroll
        for (int ks = 0; ks < 2; ks++) {
            uint32_t ah[2][4], al[2][4];
            #pragma unroll
            for (int t = 0; t < 2; t++) {
                const float* ap = As + (mbw + t * 16 + lr) * A_PITCH + ks * 16 + 2 * lc;
                float2 f0 = *(const float2*)(ap);
                float2 f1 = *(const float2*)(ap + 8 * A_PITCH);
                float2 f2 = *(const float2*)(ap + 8);
                float2 f3 = *(const float2*)(ap + 8 * A_PITCH + 8);
                cvt_pair(f0.x, f0.y, ah[t][0], al[t][0]);
                cvt_pair(f1.x, f1.y, ah[t][1], al[t][1]);
                cvt_pair(f2.x, f2.y, ah[t][2], al[t][2]);
                cvt_pair(f3.x, f3.y, ah[t][3], al[t][3]);
            }
            #pragma unroll
            for (int u = 0; u < 8; u++) {
                int rb = (nbw + u * 8 + lr) * B_PITCH + ks * 8 + lc;
                uint32_t bh0 = BHs[rb], bh1 = BHs[rb + 4];
                uint32_t bl0 = BLs[rb], bl1 = BLs[rb + 4];
                #pragma unroll
                for (int t = 0; t < 2; t++) {
                    mma_bf16(acc[t][u], ah[t], bh0, bh1);   // hi*hi
                    mma_bf16(acc[t][u], ah[t], bl0, bl1);   // hi*lo
                    mma_bf16(acc[t][u], al[t], bh0, bh1);   // lo*hi
                }
            }
        }
        __syncthreads();
    }

    // ---- epilogue ----
    #pragma unroll
    for (int t = 0; t < 2; t++) {
        int row = m0 + mbw + t * 16 + lr;
        #pragma unroll
        for (int u = 0; u < 8; u++) {
            int col = n0 + nbw + u * 8 + lc * 2;
            *(float2*)(C + (size_t)row * ldc + col) = make_float2(acc[t][u][0], acc[t][u][1]);
            *(float2*)(C + (size_t)(row + 8) * ldc + col) = make_float2(acc[t][u][2], acc[t][u][3]);
        }
    }
}

// ---------------- banded softmax mix, smem-tiled ------------------------------------------
__global__ void __launch_bounds__(256)
mix_kernel(const float* __restrict__ z, float* __restrict__ z2) {
    __shared__ float zs[96][64];
    __shared__ float ws[2 * RWIN + 1];
    const int s0 = blockIdx.x * 64;
    const int c0 = blockIdx.y * 64;
    const int b  = blockIdx.z;
    const int tid = threadIdx.x;

    if (tid < 2 * RWIN + 1) ws[tid] = g_e[tid < RWIN ? RWIN - tid : tid - RWIN];

    #pragma unroll
    for (int i = 0; i < 24; i++) {
        int idx = tid + i * 256;
        int r = idx >> 6, c = idx & 63;
        int gs = s0 - 16 + r;
        float v = 0.f;
        if ((unsigned)gs < (unsigned)SS)
            v = z[((size_t)b * SS + gs) * CP + c0 + c];
        zs[r][c] = v;
    }
    __syncthreads();

    const int c = tid & 63;
    #pragma unroll 4
    for (int is = 0; is < 16; is++) {
        int sl = (tid >> 6) + is * 4;
        int s = s0 + sl;
        float Z = 0.f, acc2 = 0.f;
        #pragma unroll
        for (int d = -RWIN; d <= RWIN; ++d) {
            int t = s - d;
            if ((unsigned)t < (unsigned)SS) {
                float w = ws[d + RWIN];
                Z += w;
                acc2 += w * zs[sl + 16 - d][c];
            }
        }
        z2[((size_t)b * SS + s) * CP + c0 + c] = acc2 * (1.f / Z);
    }
}

// ---------------- launch ------------------------------------------------------------------
extern "C" void kernel_launch(void* const* d_in, const int* in_sizes, int n_in,
                              void* d_out, int out_size) {
    const float* x      = (const float*)d_in[0];
    const float* v_low  = (const float*)d_in[5];   // [242, 768]
    const float* v_high = (const float*)d_in[6];   // [256, 242]
    const float* o_low  = (const float*)d_in[7];   // [242, 256]
    const float* o_high = (const float*)d_in[8];   // [768, 242]
    float* out = (float*)d_out;                    // [4, 4096, 768]

    float* z   = nullptr; cudaGetSymbolAddress((void**)&z,   g_z);
    float* z2  = nullptr; cudaGetSymbolAddress((void**)&z2,  g_z2);
    float* T1t = nullptr; cudaGetSymbolAddress((void**)&T1t, g_T1t);
    float* WcT = nullptr; cudaGetSymbolAddress((void**)&WcT, g_WcT);
    __nv_bfloat16* vlh = nullptr; cudaGetSymbolAddress((void**)&vlh, g_vlh);
    __nv_bfloat16* vll = nullptr; cudaGetSymbolAddress((void**)&vll, g_vll);
    __nv_bfloat16* wch = nullptr; cudaGetSymbolAddress((void**)&wch, g_wch);
    __nv_bfloat16* wcl = nullptr; cudaGetSymbolAddress((void**)&wcl, g_wcl);

    cudaFuncSetAttribute(mma_gemm_abt, cudaFuncAttributeMaxDynamicSharedMemorySize, SM_BYTES);

    // 1. band weights
    prep_kernel<<<1, (RWIN + 1) * 32>>>();

    // 2. v_low -> bf16 hi/lo, zero-padded to 256 rows
    conv_hilo<<<(CP * HH + 255) / 256, 256>>>(v_low, RR, HH, vlh, vll, CP);

    // 3. T1t[242,242] = o_low[242,256] @ v_high[256,242]
    gemm_nn_small<<<dim3((RR + 15) / 16, (RR + 15) / 16), dim3(16, 16)>>>(
        o_low, HK, v_high, RR, T1t, RR, RR, RR, HK);

    // 4. WcT[768,256] = o_high[768,242] @ T1t[242,242]  (cols 242..255 stay zero)
    gemm_nn_small<<<dim3((RR + 15) / 16, (HH + 15) / 16), dim3(16, 16)>>>(
        o_high, RR, T1t, RR, WcT, CP, HH, RR, RR);

    // 5. WcT -> bf16 hi/lo
    conv_hilo<<<(HH * CP + 255) / 256, 256>>>(WcT, HH, CP, wch, wcl, HH);

    // 6. z = x @ v_low^T   [16384, 256]
    mma_gemm_abt<<<dim3(CP / 128, (BB * SS) / 128), 256, SM_BYTES>>>(
        x, HH, vlh, vll, HH, z, CP, HH);

    // 7. banded softmax mix
    mix_kernel<<<dim3(SS / 64, CP / 64, BB), 256>>>(z, z2);

    // 8. out = z2 @ WcT^T  [16384, 768]
    mma_gemm_abt<<<dim3(HH / 128, (BB * SS) / 128), 256, SM_BYTES>>>(
        z2, CP, wch, wcl, CP, out, HH, CP);

    (void)in_sizes; (void)n_in; (void)out_size;
}